// round 4
// baseline (speedup 1.0000x reference)
#include <cuda_runtime.h>
#include <cstdint>

#define NROWS 16384
#define DIN   4096
#define DOUT  4096
#define RNK   64
#define KTOP  8

#define DIN4  (DIN/4)    // 1024
#define DOUT4 (DOUT/4)   // 1024

#define NBLK  296        // 2 CTAs/SM x 148 SMs (all co-resident; GB300 has 152 SMs)
#define THR   256        // 8 warps
#define RPB   56         // rows per block in phase A (296*56 = 16576 >= 16384, clamped)
#define RPW   7          // rows per warp (8 warps * 7 = 56)

#define NTILE 32         // 128-wide output tiles (4096/128)
#define NSPL  37         // row splits in phase B: 32*37 = 1184 = 4*296 items exactly
#define RSPL  443        // rows per split (37*443 = 16391 >= 16384, clamped)

// ---- scratch (device globals; no allocations allowed) ----
__device__ float4 g_G[NROWS * 2];                  // gathered*scaled values, [n][8]
__device__ uint2  g_pidx[NROWS];                   // 8x 6-bit indices packed as bytes
__device__ __align__(16) float g_uwT[RNK * DOUT];  // up_w transposed to [64][4096]
__device__ unsigned g_cnt;                         // grid barrier arrival count (zero-init)
__device__ unsigned g_gen;                         // grid barrier generation

__device__ __forceinline__ void grid_barrier()
{
    __threadfence();          // make this block's global writes visible
    __syncthreads();
    if (threadIdx.x == 0) {
        unsigned gen = *(volatile unsigned*)&g_gen;      // read BEFORE arriving
        if (atomicAdd(&g_cnt, 1u) == NBLK - 1u) {
            atomicExch(&g_cnt, 0u);
            __threadfence();
            atomicAdd(&g_gen, 1u);
        } else {
            while (*(volatile unsigned*)&g_gen == gen) { }
        }
    }
    __syncthreads();
}

__global__ __launch_bounds__(THR, 2) void moe_fused(
    const float* __restrict__ x, const float* __restrict__ dw,
    const float* __restrict__ uw, const float* __restrict__ tv,
    const long long* __restrict__ ti, float* __restrict__ out)
{
    __shared__ float4 Wsm[RNK * 32];   // 32 KB: phase A down_w chunk / phase B up_wT tile
    __shared__ uint2  sidx[RPB];

    const int tid  = threadIdx.x;
    const int wid  = tid >> 5;
    const int lane = tid & 31;
    const int bid  = blockIdx.x;

    // ================= phase T: transpose up_w -> g_uwT [64][4096] ============
    for (int i = bid * THR + tid; i < RNK * DOUT; i += NBLK * THR) {
        int r = i >> 12, o = i & (DOUT - 1);
        g_uwT[i] = uw[o * RNK + r];               // coalesced store
    }

    // ================= phase A: sparse down-projection ========================
    // dtype detection, in-bounds for both int32 and int64 index data:
    // int64 indices in [0,64) have zero high words at odd int32 positions 1..15;
    // int32 data there holds real distinct-per-row indices -> OR != 0.
    const int* t32base = (const int*)ti;
    const bool is64 = ((t32base[1] | t32base[3] | t32base[5] | t32base[7] |
                        t32base[9] | t32base[11] | t32base[13] | t32base[15]) == 0);

    const int row0 = bid * RPB;

    // pack top-k indices: lanes 0..6 of each warp handle one of its 7 rows
    if (lane < RPW) {
        int r    = wid * RPW + lane;
        int row  = row0 + r;
        int rowc = row < NROWS ? row : NROWS - 1;
        unsigned lo = 0, hi = 0;
        if (is64) {
            const long long* t64 = ti + (size_t)rowc * KTOP;
            #pragma unroll
            for (int k = 0; k < 4; k++) {
                lo |= ((unsigned)t64[k]     & 63u) << (8 * k);
                hi |= ((unsigned)t64[4 + k] & 63u) << (8 * k);
            }
        } else {
            const int* t32 = t32base + (size_t)rowc * KTOP;
            #pragma unroll
            for (int k = 0; k < 4; k++) {
                lo |= ((unsigned)t32[k]     & 63u) << (8 * k);
                hi |= ((unsigned)t32[4 + k] & 63u) << (8 * k);
            }
        }
        uint2 p; p.x = lo; p.y = hi;
        sidx[r] = p;
        if (row < NROWS) g_pidx[row] = p;
    }
    __syncthreads();

    uint2 pk[RPW];
    #pragma unroll
    for (int r7 = 0; r7 < RPW; r7++) pk[r7] = sidx[wid * RPW + r7];

    float acc[RPW][8];
    #pragma unroll
    for (int i = 0; i < RPW; i++)
        #pragma unroll
        for (int k = 0; k < 8; k++) acc[i][k] = 0.f;

    const float4* x4  = (const float4*)x;
    const float4* dw4 = (const float4*)dw;

    #pragma unroll 1
    for (int c = 0; c < DIN4 / 32; c++) {         // 32 chunks of 128 cols
        // stage down_w chunk [64][128] into SMEM (coalesced float4)
        #pragma unroll
        for (int t = 0; t < 8; t++) {
            int lin = tid + t * THR;              // 0..2047
            Wsm[lin] = dw4[(lin >> 5) * DIN4 + c * 32 + (lin & 31)];
        }
        __syncthreads();

        #pragma unroll
        for (int r7 = 0; r7 < RPW; r7++) {
            int row  = row0 + wid * RPW + r7;
            int rowc = row < NROWS ? row : NROWS - 1;
            float4 xv = x4[(size_t)rowc * DIN4 + c * 32 + lane];
            unsigned lo = pk[r7].x, hi = pk[r7].y;
            #pragma unroll
            for (int k = 0; k < 8; k++) {
                unsigned bits = (k < 4) ? lo : hi;
                unsigned idx  = (bits >> (8 * (k & 3))) & 63u;
                float4 wv = Wsm[idx * 32 + lane];  // uniform idx per warp -> conflict-free
                float a = acc[r7][k];
                a = fmaf(xv.x, wv.x, a);
                a = fmaf(xv.y, wv.y, a);
                a = fmaf(xv.z, wv.z, a);
                a = fmaf(xv.w, wv.w, a);
                acc[r7][k] = a;
            }
        }
        __syncthreads();
    }

    // reduce across lanes, scale, store G
    #pragma unroll
    for (int r7 = 0; r7 < RPW; r7++) {
        int row = row0 + wid * RPW + r7;
        #pragma unroll
        for (int k = 0; k < 8; k++) {
            float vsum = acc[r7][k];
            vsum += __shfl_xor_sync(0xffffffffu, vsum, 16);
            vsum += __shfl_xor_sync(0xffffffffu, vsum, 8);
            vsum += __shfl_xor_sync(0xffffffffu, vsum, 4);
            vsum += __shfl_xor_sync(0xffffffffu, vsum, 2);
            vsum += __shfl_xor_sync(0xffffffffu, vsum, 1);
            if (lane == k && row < NROWS) {
                ((float*)g_G)[(size_t)row * KTOP + k] = vsum * tv[(size_t)row * KTOP + k];
            }
        }
    }

    // ============ all G / pidx / uwT must be visible chip-wide ================
    grid_barrier();

    // ================= phase B: sparse up-projection ==========================
    const float4* uwT4 = (const float4*)g_uwT;
    float4* out4 = (float4*)out;

    #pragma unroll 1
    for (int j = 0; j < 4; j++) {                 // 1184 items = 4 per block exactly
        int item  = bid + j * NBLK;
        int tile  = item & (NTILE - 1);           // 0..31
        int split = item >> 5;                    // 0..36
        int ob4   = tile * 32;                    // float4 offset into DOUT4

        // stage up_wT tile [64][128] into SMEM
        #pragma unroll
        for (int t = 0; t < 8; t++) {
            int lin = tid + t * THR;
            Wsm[lin] = uwT4[(lin >> 5) * DOUT4 + ob4 + (lin & 31)];
        }
        __syncthreads();

        int n    = split * RSPL + wid;
        int nend = min(split * RSPL + RSPL, NROWS);

        if (n < nend) {
            uint2  p  = g_pidx[n];
            float4 Ga = g_G[n * 2];
            float4 Gb = g_G[n * 2 + 1];

            while (n < nend) {
                int n2 = n + 8;
                uint2 pn; float4 Gan, Gbn;
                if (n2 < nend) {                  // prefetch next row's metadata
                    pn  = g_pidx[n2];
                    Gan = g_G[n2 * 2];
                    Gbn = g_G[n2 * 2 + 1];
                }

                float4 a; a.x = a.y = a.z = a.w = 0.f;
                float4 w;
                unsigned i0 =  p.x        & 63u;
                unsigned i1 = (p.x >> 8)  & 63u;
                unsigned i2 = (p.x >> 16) & 63u;
                unsigned i3 = (p.x >> 24) & 63u;
                unsigned i4 =  p.y        & 63u;
                unsigned i5 = (p.y >> 8)  & 63u;
                unsigned i6 = (p.y >> 16) & 63u;
                unsigned i7 = (p.y >> 24) & 63u;

                w = Wsm[i0 * 32 + lane];
                a.x = fmaf(Ga.x, w.x, a.x); a.y = fmaf(Ga.x, w.y, a.y); a.z = fmaf(Ga.x, w.z, a.z); a.w = fmaf(Ga.x, w.w, a.w);
                w = Wsm[i1 * 32 + lane];
                a.x = fmaf(Ga.y, w.x, a.x); a.y = fmaf(Ga.y, w.y, a.y); a.z = fmaf(Ga.y, w.z, a.z); a.w = fmaf(Ga.y, w.w, a.w);
                w = Wsm[i2 * 32 + lane];
                a.x = fmaf(Ga.z, w.x, a.x); a.y = fmaf(Ga.z, w.y, a.y); a.z = fmaf(Ga.z, w.z, a.z); a.w = fmaf(Ga.z, w.w, a.w);
                w = Wsm[i3 * 32 + lane];
                a.x = fmaf(Ga.w, w.x, a.x); a.y = fmaf(Ga.w, w.y, a.y); a.z = fmaf(Ga.w, w.z, a.z); a.w = fmaf(Ga.w, w.w, a.w);
                w = Wsm[i4 * 32 + lane];
                a.x = fmaf(Gb.x, w.x, a.x); a.y = fmaf(Gb.x, w.y, a.y); a.z = fmaf(Gb.x, w.z, a.z); a.w = fmaf(Gb.x, w.w, a.w);
                w = Wsm[i5 * 32 + lane];
                a.x = fmaf(Gb.y, w.x, a.x); a.y = fmaf(Gb.y, w.y, a.y); a.z = fmaf(Gb.y, w.z, a.z); a.w = fmaf(Gb.y, w.w, a.w);
                w = Wsm[i6 * 32 + lane];
                a.x = fmaf(Gb.z, w.x, a.x); a.y = fmaf(Gb.z, w.y, a.y); a.z = fmaf(Gb.z, w.z, a.z); a.w = fmaf(Gb.z, w.w, a.w);
                w = Wsm[i7 * 32 + lane];
                a.x = fmaf(Gb.w, w.x, a.x); a.y = fmaf(Gb.w, w.y, a.y); a.z = fmaf(Gb.w, w.z, a.z); a.w = fmaf(Gb.w, w.w, a.w);

                out4[(size_t)n * DOUT4 + ob4 + lane] = a;

                p = pn; Ga = Gan; Gb = Gbn; n = n2;
            }
        }
        __syncthreads();
    }
}

// =====================================================================
extern "C" void kernel_launch(void* const* d_in, const int* in_sizes, int n_in,
                              void* d_out, int out_size)
{
    const float*     x  = (const float*)d_in[0];      // hidden_states [16384,4096]
    const float*     dw = (const float*)d_in[1];      // down_w [64,4096]
    const float*     uw = (const float*)d_in[2];      // up_w [4096,64]
    const float*     tv = (const float*)d_in[3];      // top_k_values [16384,8]
    const long long* ti = (const long long*)d_in[4];  // top_k_indices (i64/i32 auto)

    moe_fused<<<NBLK, THR>>>(x, dw, uw, tv, ti, (float*)d_out);
}

// round 5
// speedup vs baseline: 1.1092x; 1.1092x over previous
#include <cuda_runtime.h>
#include <cstdint>

#define NROWS 16384
#define DIN   4096
#define DOUT  4096
#define RNK   64
#define KTOP  8

#define DIN4  (DIN/4)    // 1024
#define DOUT4 (DOUT/4)   // 1024

#define NBLK  256        // co-resident: <= 2 CTAs/SM x 148 SMs
#define THR   512        // 16 warps
#define RPW   4          // rows per warp in phase A
#define RPB   64         // rows per block = 16 warps * 4  (256*64 = 16384 exactly)

#define NTILE 32         // 128-wide output tiles (4096/128)
#define NSPL  8          // row splits in phase B: 32*8 = 256 items = 1 per block
#define RSPL  2048       // rows per split (8*2048 = 16384 exactly)

// ---- scratch (device globals; no allocations allowed) ----
__device__ float4 g_G[NROWS * 2];                  // gathered*scaled values, [n][8]
__device__ uint2  g_pidx[NROWS];                   // 8x 6-bit indices packed as bytes
__device__ __align__(16) float g_uwT[RNK * DOUT];  // up_w transposed to [64][4096]
__device__ unsigned g_cnt;                         // grid barrier arrival count (zero-init)
__device__ unsigned g_gen;                         // grid barrier generation

__device__ __forceinline__ void grid_barrier()
{
    __threadfence();
    __syncthreads();
    if (threadIdx.x == 0) {
        unsigned gen = *(volatile unsigned*)&g_gen;      // read BEFORE arriving
        if (atomicAdd(&g_cnt, 1u) == NBLK - 1u) {
            atomicExch(&g_cnt, 0u);
            __threadfence();
            atomicAdd(&g_gen, 1u);
        } else {
            while (*(volatile unsigned*)&g_gen == gen) { }
        }
    }
    __syncthreads();
}

__global__ __launch_bounds__(THR, 2) void moe_fused(
    const float* __restrict__ x, const float* __restrict__ dw,
    const float* __restrict__ uw, const float* __restrict__ tv,
    const long long* __restrict__ ti, float* __restrict__ out)
{
    __shared__ float4 Wsm[RNK * 32];   // 32 KB: phase A down_w chunk / phase B up_wT tile
    __shared__ uint2  sidx[RPB];

    const int tid  = threadIdx.x;
    const int wid  = tid >> 5;         // 0..15
    const int lane = tid & 31;
    const int bid  = blockIdx.x;

    // ================= phase T: transpose up_w -> g_uwT [64][4096] ============
    for (int i = bid * THR + tid; i < RNK * DOUT; i += NBLK * THR) {
        int r = i >> 12, o = i & (DOUT - 1);
        g_uwT[i] = uw[o * RNK + r];               // coalesced store
    }

    // ================= phase A: sparse down-projection ========================
    // dtype detection, in-bounds for both int32 and int64 index data:
    // int64 indices in [0,64) have zero high words at odd int32 positions 1..15;
    // int32 data there holds real distinct-per-row indices -> OR != 0.
    const int* t32base = (const int*)ti;
    const bool is64 = ((t32base[1] | t32base[3] | t32base[5] | t32base[7] |
                        t32base[9] | t32base[11] | t32base[13] | t32base[15]) == 0);

    const int row0 = bid * RPB;

    // pack top-k indices: lanes 0..3 of each warp handle one of its 4 rows
    if (lane < RPW) {
        int r   = wid * RPW + lane;
        int row = row0 + r;
        unsigned lo = 0, hi = 0;
        if (is64) {
            const long long* t64 = ti + (size_t)row * KTOP;
            #pragma unroll
            for (int k = 0; k < 4; k++) {
                lo |= ((unsigned)t64[k]     & 63u) << (8 * k);
                hi |= ((unsigned)t64[4 + k] & 63u) << (8 * k);
            }
        } else {
            const int* t32 = t32base + (size_t)row * KTOP;
            #pragma unroll
            for (int k = 0; k < 4; k++) {
                lo |= ((unsigned)t32[k]     & 63u) << (8 * k);
                hi |= ((unsigned)t32[4 + k] & 63u) << (8 * k);
            }
        }
        uint2 p; p.x = lo; p.y = hi;
        sidx[r]    = p;
        g_pidx[row] = p;
    }
    __syncthreads();

    uint2 pk[RPW];
    #pragma unroll
    for (int r4 = 0; r4 < RPW; r4++) pk[r4] = sidx[wid * RPW + r4];

    float acc[RPW][8];
    #pragma unroll
    for (int i = 0; i < RPW; i++)
        #pragma unroll
        for (int k = 0; k < 8; k++) acc[i][k] = 0.f;

    const float4* x4  = (const float4*)x;
    const float4* dw4 = (const float4*)dw;

    #pragma unroll 1
    for (int c = 0; c < DIN4 / 32; c++) {         // 32 chunks of 128 cols
        // stage down_w chunk [64][128] into SMEM (coalesced float4, 4 per thread)
        #pragma unroll
        for (int t = 0; t < 4; t++) {
            int lin = tid + t * THR;              // 0..2047
            Wsm[lin] = dw4[(lin >> 5) * DIN4 + c * 32 + (lin & 31)];
        }
        __syncthreads();

        #pragma unroll
        for (int r4 = 0; r4 < RPW; r4++) {
            int row = row0 + wid * RPW + r4;
            float4 xv = x4[(size_t)row * DIN4 + c * 32 + lane];
            unsigned lo = pk[r4].x, hi = pk[r4].y;
            #pragma unroll
            for (int k = 0; k < 8; k++) {
                unsigned bits = (k < 4) ? lo : hi;
                unsigned idx  = (bits >> (8 * (k & 3))) & 63u;
                float4 wv = Wsm[idx * 32 + lane];  // uniform idx per warp -> conflict-free
                float a = acc[r4][k];
                a = fmaf(xv.x, wv.x, a);
                a = fmaf(xv.y, wv.y, a);
                a = fmaf(xv.z, wv.z, a);
                a = fmaf(xv.w, wv.w, a);
                acc[r4][k] = a;
            }
        }
        __syncthreads();
    }

    // reduce across lanes, scale, store G
    #pragma unroll
    for (int r4 = 0; r4 < RPW; r4++) {
        int row = row0 + wid * RPW + r4;
        #pragma unroll
        for (int k = 0; k < 8; k++) {
            float vsum = acc[r4][k];
            vsum += __shfl_xor_sync(0xffffffffu, vsum, 16);
            vsum += __shfl_xor_sync(0xffffffffu, vsum, 8);
            vsum += __shfl_xor_sync(0xffffffffu, vsum, 4);
            vsum += __shfl_xor_sync(0xffffffffu, vsum, 2);
            vsum += __shfl_xor_sync(0xffffffffu, vsum, 1);
            if (lane == k) {
                ((float*)g_G)[(size_t)row * KTOP + k] = vsum * tv[(size_t)row * KTOP + k];
            }
        }
    }

    // ============ all G / pidx must be visible chip-wide ======================
    grid_barrier();

    // ================= phase B: sparse up-projection ==========================
    // one item per block: tile = bid & 31 (128 outputs), split = bid >> 5 (2048 rows)
    const float4* uwT4 = (const float4*)g_uwT;
    float4* out4 = (float4*)out;

    const int tile  = bid & (NTILE - 1);
    const int split = bid >> 5;
    const int ob4   = tile * 32;                  // float4 offset into DOUT4

    // stage up_wT tile [64][128] into SMEM
    #pragma unroll
    for (int t = 0; t < 4; t++) {
        int lin = tid + t * THR;
        Wsm[lin] = uwT4[(lin >> 5) * DOUT4 + ob4 + (lin & 31)];
    }
    __syncthreads();

    int n = split * RSPL + wid;                   // 128 iterations, stride 16, exact

    // software pipeline depth 2
    int np1 = n + 16, np2 = min(n + 32, NROWS - 1);
    uint2  p0 = g_pidx[n];
    float4 Ga0 = g_G[n * 2],   Gb0 = g_G[n * 2 + 1];
    uint2  p1 = g_pidx[np1];
    float4 Ga1 = g_G[np1 * 2], Gb1 = g_G[np1 * 2 + 1];

    #pragma unroll 1
    for (int it = 0; it < RSPL / 16; it++) {
        // issue prefetch for iteration it+2
        uint2  p2  = g_pidx[np2];
        float4 Ga2 = g_G[np2 * 2];
        float4 Gb2 = g_G[np2 * 2 + 1];

        float4 a; a.x = a.y = a.z = a.w = 0.f;
        float4 w;
        unsigned i0 =  p0.x        & 63u;
        unsigned i1 = (p0.x >> 8)  & 63u;
        unsigned i2 = (p0.x >> 16) & 63u;
        unsigned i3 = (p0.x >> 24) & 63u;
        unsigned i4 =  p0.y        & 63u;
        unsigned i5 = (p0.y >> 8)  & 63u;
        unsigned i6 = (p0.y >> 16) & 63u;
        unsigned i7 = (p0.y >> 24) & 63u;

        w = Wsm[i0 * 32 + lane];
        a.x = fmaf(Ga0.x, w.x, a.x); a.y = fmaf(Ga0.x, w.y, a.y); a.z = fmaf(Ga0.x, w.z, a.z); a.w = fmaf(Ga0.x, w.w, a.w);
        w = Wsm[i1 * 32 + lane];
        a.x = fmaf(Ga0.y, w.x, a.x); a.y = fmaf(Ga0.y, w.y, a.y); a.z = fmaf(Ga0.y, w.z, a.z); a.w = fmaf(Ga0.y, w.w, a.w);
        w = Wsm[i2 * 32 + lane];
        a.x = fmaf(Ga0.z, w.x, a.x); a.y = fmaf(Ga0.z, w.y, a.y); a.z = fmaf(Ga0.z, w.z, a.z); a.w = fmaf(Ga0.z, w.w, a.w);
        w = Wsm[i3 * 32 + lane];
        a.x = fmaf(Ga0.w, w.x, a.x); a.y = fmaf(Ga0.w, w.y, a.y); a.z = fmaf(Ga0.w, w.z, a.z); a.w = fmaf(Ga0.w, w.w, a.w);
        w = Wsm[i4 * 32 + lane];
        a.x = fmaf(Gb0.x, w.x, a.x); a.y = fmaf(Gb0.x, w.y, a.y); a.z = fmaf(Gb0.x, w.z, a.z); a.w = fmaf(Gb0.x, w.w, a.w);
        w = Wsm[i5 * 32 + lane];
        a.x = fmaf(Gb0.y, w.x, a.x); a.y = fmaf(Gb0.y, w.y, a.y); a.z = fmaf(Gb0.y, w.z, a.z); a.w = fmaf(Gb0.y, w.w, a.w);
        w = Wsm[i6 * 32 + lane];
        a.x = fmaf(Gb0.z, w.x, a.x); a.y = fmaf(Gb0.z, w.y, a.y); a.z = fmaf(Gb0.z, w.z, a.z); a.w = fmaf(Gb0.z, w.w, a.w);
        w = Wsm[i7 * 32 + lane];
        a.x = fmaf(Gb0.w, w.x, a.x); a.y = fmaf(Gb0.w, w.y, a.y); a.z = fmaf(Gb0.w, w.z, a.z); a.w = fmaf(Gb0.w, w.w, a.w);

        out4[(size_t)n * DOUT4 + ob4 + lane] = a;

        // rotate pipeline
        n = np1; np1 = np2; np2 = min(np1 + 16, NROWS - 1);
        p0 = p1; Ga0 = Ga1; Gb0 = Gb1;
        p1 = p2; Ga1 = Ga2; Gb1 = Gb2;
    }
}

// =====================================================================
extern "C" void kernel_launch(void* const* d_in, const int* in_sizes, int n_in,
                              void* d_out, int out_size)
{
    const float*     x  = (const float*)d_in[0];      // hidden_states [16384,4096]
    const float*     dw = (const float*)d_in[1];      // down_w [64,4096]
    const float*     uw = (const float*)d_in[2];      // up_w [4096,64]
    const float*     tv = (const float*)d_in[3];      // top_k_values [16384,8]
    const long long* ti = (const long long*)d_in[4];  // top_k_indices (i64/i32 auto)

    moe_fused<<<NBLK, THR>>>(x, dw, uw, tv, ti, (float*)d_out);
}